// round 10
// baseline (speedup 1.0000x reference)
#include <cuda_runtime.h>

// LSTMAnomalyDetector: B=4096, T=512, I=3, H=64 (PyTorch gate order i,f,g,o)
//
// Round-10: k-split. grid=256 x NT=256, RT=16 rows/CTA, 2 CTAs/SM.
// Thread (u, rg, kh) computes PARTIAL gate sums for unit u, rows 8rg..8rg+7,
// k in [32*kh, 32*kh+32). Pair (kh=0,1) = adjacent lanes; one shfl.bfly
// combines partials, after which each thread owns 4 rows (rq = tid&3) for
// the nonlinearity + h store. Same per-k mix as round 9 (5 LDS.128 : 16 fma2)
// but 16 warps/SM instead of 8 -> latency hiding doubles at equal pipe floor.

#define B_   4096
#define T_   512
#define H_   64
#define RT   16      // rows per CTA
#define NT   256     // threads per CTA
#define HPD  18      // hdup row pitch in ulls (16 used + pad)
#define KH   32      // k per thread (H_/2)

typedef unsigned long long ull;

__device__ __forceinline__ float tanhfast(float x) {
    float y; asm("tanh.approx.f32 %0, %1;" : "=f"(y) : "f"(x)); return y;
}
__device__ __forceinline__ float sigf(float x) {
    return fmaf(0.5f, tanhfast(0.5f * x), 0.5f);
}
__device__ __forceinline__ ull pack2(float a, float b) {   // a -> low lane
    ull r; asm("mov.b64 %0, {%1, %2};" : "=l"(r) : "f"(a), "f"(b)); return r;
}
__device__ __forceinline__ void unpack2(ull v, float& lo, float& hi) {
    asm("mov.b64 {%0, %1}, %2;" : "=f"(lo), "=f"(hi) : "l"(v));
}
__device__ __forceinline__ ull fma2(ull a, ull b, ull c) {
    ull d; asm("fma.rn.f32x2 %0, %1, %2, %3;" : "=l"(d) : "l"(a), "l"(b), "l"(c)); return d;
}
__device__ __forceinline__ ull add2(ull a, ull b) {
    ull d; asm("add.rn.f32x2 %0, %1, %2;" : "=l"(d) : "l"(a), "l"(b)); return d;
}
// 64-bit butterfly shuffle with partner = lane ^ 1
__device__ __forceinline__ ull shfl_bfly64_1(ull v) {
    unsigned lo, hi;
    asm("mov.b64 {%0, %1}, %2;" : "=r"(lo), "=r"(hi) : "l"(v));
    unsigned plo, phi;
    asm("shfl.sync.bfly.b32 %0, %1, 1, 0x1F, 0xFFFFFFFF;" : "=r"(plo) : "r"(lo));
    asm("shfl.sync.bfly.b32 %0, %1, 1, 0x1F, 0xFFFFFFFF;" : "=r"(phi) : "r"(hi));
    ull r;
    asm("mov.b64 %0, {%1, %2};" : "=l"(r) : "r"(plo), "r"(phi));
    return r;
}

struct Smem {
    ulonglong2 W4[H_][H_];     // 64KB [k][u]: .x=(wi,wf) .y=(wg,wo)
    ull hdup[2][H_][HPD];      // 18KB [buf][unit][row]: (h,h) duplicated
    ull xdup[2][3][RT];        // [buf][comp][row]: (x,x) duplicated
    float wdec[3][H_];
};
#define SMEM_BYTES ((int)sizeof(Smem))

extern __shared__ char smem_raw[];

__global__ void __launch_bounds__(NT, 2)
lstm_persistent_kernel(const float* __restrict__ x,      // [B, T, 3]
                       const float* __restrict__ Wih,    // [256, 3]
                       const float* __restrict__ Whh,    // [256, 64]
                       const float* __restrict__ bih,    // [256]
                       const float* __restrict__ bhh,    // [256]
                       const float* __restrict__ Wdec,   // [3, 64]
                       const float* __restrict__ bdec,   // [3]
                       float* __restrict__ out)          // [B, T, 3]
{
    Smem* S = (Smem*)smem_raw;
    const int tid  = threadIdx.x;
    const int row0 = blockIdx.x * RT;

    const int u  = tid >> 2;        // unit 0..63
    const int rg = (tid >> 1) & 1;  // matvec rows 8rg .. 8rg+7
    const int kh = tid & 1;         // k half: [32*kh, 32*kh+32)
    const int rq = tid & 3;         // final ownership: rows 4rq .. 4rq+3

    // ---- setup -----------------------------------------------------------
    for (int idx = tid; idx < H_ * H_; idx += NT) {
        const int k = idx >> 6, uu = idx & 63;
        const float wi = Whh[(0 * H_ + uu) * H_ + k];
        const float wf = Whh[(1 * H_ + uu) * H_ + k];
        const float wg = Whh[(2 * H_ + uu) * H_ + k];
        const float wo = Whh[(3 * H_ + uu) * H_ + k];
        *(float4*)&S->W4[k][uu] = make_float4(wi, wf, wg, wo);
    }
    for (int i = tid; i < 2 * H_ * HPD; i += NT) ((ull*)S->hdup)[i] = 0ull;
    for (int i = tid; i < 3 * H_; i += NT) ((float*)S->wdec)[i] = Wdec[i];

    // bias / W_ih (gate-packed); only kh==0 applies them (added once per pair)
    const ull bias_if = pack2(bih[u]        + bhh[u],
                              bih[H_ + u]   + bhh[H_ + u]);
    const ull bias_go = pack2(bih[2*H_ + u] + bhh[2*H_ + u],
                              bih[3*H_ + u] + bhh[3*H_ + u]);
    ull wih_if[3], wih_go[3];
#pragma unroll
    for (int i = 0; i < 3; i++) {
        wih_if[i] = pack2(Wih[u * 3 + i],          Wih[(H_ + u) * 3 + i]);
        wih_go[i] = pack2(Wih[(2*H_ + u) * 3 + i], Wih[(3*H_ + u) * 3 + i]);
    }

    // decode / x-staging roles: threads 0..47 -> (comp o, row r)
    const int o_ = tid >> 4;        // 0..2 (for tid<48)
    const int r_ = tid & 15;        // 0..15
    float bd = 0.0f;
    if (tid < 48) {
        bd = bdec[o_];
        const float xv = x[((size_t)(row0 + r_) * T_ + 0) * 3 + o_];
        S->xdup[0][o_][r_] = pack2(xv, xv);
    }

    float c[4];                     // cell state for rows 4rq..4rq+3 (fixed owner)
#pragma unroll
    for (int p = 0; p < 4; p++) c[p] = 0.0f;

    __syncthreads();

    // ---- timestep loop -----------------------------------------------------
    for (int t = 0; t < T_; t++) {
        const int A = t & 1, Bb = A ^ 1;

        float xp = 0.0f;
        if (tid < 48 && (t + 1) < T_)
            xp = x[((size_t)(row0 + r_) * T_ + (t + 1)) * 3 + o_];

        // decode previous step's h -> out[., t-1, .]
        if (t > 0 && tid < 48) {
            const float* hp_ = (const float*)&S->hdup[A][0][r_];  // low lane of (h,h)
            const float* wd  = &S->wdec[o_][0];
            float s0 = 0.f, s1 = 0.f, s2 = 0.f, s3 = 0.f;
#pragma unroll 4
            for (int k = 0; k < H_; k += 4) {
                s0 = fmaf(hp_[(k + 0) * (2 * HPD)], wd[k + 0], s0);
                s1 = fmaf(hp_[(k + 1) * (2 * HPD)], wd[k + 1], s1);
                s2 = fmaf(hp_[(k + 2) * (2 * HPD)], wd[k + 2], s2);
                s3 = fmaf(hp_[(k + 3) * (2 * HPD)], wd[k + 3], s3);
            }
            out[((size_t)(row0 + r_) * T_ + (t - 1)) * 3 + o_] = (s0 + s1) + (s2 + s3) + bd;
        }

        // partial accumulators for rows 8rg+j, j=0..7
        ull aif[8], ago[8];
        if (kh == 0) {
#pragma unroll
            for (int j = 0; j < 8; j++) { aif[j] = bias_if; ago[j] = bias_go; }
#pragma unroll
            for (int i = 0; i < 3; i++) {
                const ulonglong2* xp2 = (const ulonglong2*)&S->xdup[A][i][8 * rg];
#pragma unroll
                for (int q = 0; q < 4; q++) {
                    const ulonglong2 xv = xp2[q];
                    aif[2*q]   = fma2(xv.x, wih_if[i], aif[2*q]);
                    ago[2*q]   = fma2(xv.x, wih_go[i], ago[2*q]);
                    aif[2*q+1] = fma2(xv.y, wih_if[i], aif[2*q+1]);
                    ago[2*q+1] = fma2(xv.y, wih_go[i], ago[2*q+1]);
                }
            }
        } else {
#pragma unroll
            for (int j = 0; j < 8; j++) { aif[j] = 0ull; ago[j] = 0ull; }
        }

        // partial recurrent matvec over my 32 k's: per k, 5x LDS.128 + 16x fma2
        {
            const ulonglong2* wp = &S->W4[KH * kh][u];       // stride H_ per k
            const ull* hp = &S->hdup[A][KH * kh][8 * rg];    // stride HPD per k
#pragma unroll 4
            for (int k = 0; k < KH; k++) {
                const ulonglong2 wv = *wp;
                const ulonglong2 h01 = *(const ulonglong2*)(hp + 0);
                const ulonglong2 h23 = *(const ulonglong2*)(hp + 2);
                const ulonglong2 h45 = *(const ulonglong2*)(hp + 4);
                const ulonglong2 h67 = *(const ulonglong2*)(hp + 6);
                aif[0] = fma2(h01.x, wv.x, aif[0]);
                ago[0] = fma2(h01.x, wv.y, ago[0]);
                aif[1] = fma2(h01.y, wv.x, aif[1]);
                ago[1] = fma2(h01.y, wv.y, ago[1]);
                aif[2] = fma2(h23.x, wv.x, aif[2]);
                ago[2] = fma2(h23.x, wv.y, ago[2]);
                aif[3] = fma2(h23.y, wv.x, aif[3]);
                ago[3] = fma2(h23.y, wv.y, ago[3]);
                aif[4] = fma2(h45.x, wv.x, aif[4]);
                ago[4] = fma2(h45.x, wv.y, ago[4]);
                aif[5] = fma2(h45.y, wv.x, aif[5]);
                ago[5] = fma2(h45.y, wv.y, ago[5]);
                aif[6] = fma2(h67.x, wv.x, aif[6]);
                ago[6] = fma2(h67.x, wv.y, ago[6]);
                aif[7] = fma2(h67.y, wv.x, aif[7]);
                ago[7] = fma2(h67.y, wv.y, ago[7]);
                wp += H_;
                hp += HPD;
            }
        }

        // pair-combine partials with the lane^1 partner.
        // kh=0 keeps rows j=0..3 (global 8rg+j = 4rq+j), kh=1 keeps j=4..7.
        // Each thread SENDS the half it doesn't keep; bfly returns partner's send,
        // which is exactly the partial for the half it keeps.
        ull oif[4], ogo[4];
#pragma unroll
        for (int jj = 0; jj < 4; jj++) {
            const ull s_if = kh ? aif[jj] : aif[4 + jj];
            const ull s_go = kh ? ago[jj] : ago[4 + jj];
            const ull m_if = kh ? aif[4 + jj] : aif[jj];
            const ull m_go = kh ? ago[4 + jj] : ago[jj];
            oif[jj] = add2(m_if, shfl_bfly64_1(s_if));
            ogo[jj] = add2(m_go, shfl_bfly64_1(s_go));
        }

        // nonlinearities + state update on 4 (row = 4rq+jj, unit u) cells
        float hout[4];
#pragma unroll
        for (int jj = 0; jj < 4; jj++) {
            float gi, gf, gg, go;
            unpack2(oif[jj], gi, gf);
            unpack2(ogo[jj], gg, go);
            const float ig = sigf(gi), fg = sigf(gf);
            const float gt = tanhfast(gg), og = sigf(go);
            const float cn = fmaf(fg, c[jj], ig * gt);
            c[jj] = cn;
            hout[jj] = og * tanhfast(cn);
        }
        {
            ull* hd = &S->hdup[Bb][u][4 * rq];
            ulonglong2 v0, v1;
            v0.x = pack2(hout[0], hout[0]);
            v0.y = pack2(hout[1], hout[1]);
            v1.x = pack2(hout[2], hout[2]);
            v1.y = pack2(hout[3], hout[3]);
            *(ulonglong2*)(hd + 0) = v0;
            *(ulonglong2*)(hd + 2) = v1;
        }

        if (tid < 48) S->xdup[Bb][o_][r_] = pack2(xp, xp);

        __syncthreads();
    }

    // epilogue: decode h(T-1) (last store went to buffer 0)
    if (tid < 48) {
        const float* hp_ = (const float*)&S->hdup[0][0][r_];
        const float* wd  = &S->wdec[o_][0];
        float s0 = 0.f, s1 = 0.f, s2 = 0.f, s3 = 0.f;
#pragma unroll 4
        for (int k = 0; k < H_; k += 4) {
            s0 = fmaf(hp_[(k + 0) * (2 * HPD)], wd[k + 0], s0);
            s1 = fmaf(hp_[(k + 1) * (2 * HPD)], wd[k + 1], s1);
            s2 = fmaf(hp_[(k + 2) * (2 * HPD)], wd[k + 2], s2);
            s3 = fmaf(hp_[(k + 3) * (2 * HPD)], wd[k + 3], s3);
        }
        out[((size_t)(row0 + r_) * T_ + (T_ - 1)) * 3 + o_] = (s0 + s1) + (s2 + s3) + bd;
    }
}

extern "C" void kernel_launch(void* const* d_in, const int* in_sizes, int n_in,
                              void* d_out, int out_size) {
    const float* x    = (const float*)d_in[0];
    const float* Wih  = (const float*)d_in[1];
    const float* Whh  = (const float*)d_in[2];
    const float* bih  = (const float*)d_in[3];
    const float* bhh  = (const float*)d_in[4];
    const float* Wdec = (const float*)d_in[5];
    const float* bdec = (const float*)d_in[6];
    float* out = (float*)d_out;

    cudaFuncSetAttribute(lstm_persistent_kernel,
                         cudaFuncAttributeMaxDynamicSharedMemorySize, SMEM_BYTES);
    lstm_persistent_kernel<<<B_ / RT, NT, SMEM_BYTES>>>(x, Wih, Whh, bih, bhh, Wdec, bdec, out);
}

// round 11
// speedup vs baseline: 2.4350x; 2.4350x over previous
#include <cuda_runtime.h>

// LSTMAnomalyDetector: B=4096, T=512, I=3, H=64 (PyTorch gate order i,f,g,o)
//
// Round-11: warp-granular k-split. grid=256 x NT=256, RT=16 rows/CTA, 2 CTAs/SM
// -> 16 warps/SM. Threads 0-127 (kh=0) accumulate k in [0,32) (+bias+Wih*x);
// threads 128-255 (kh=1) accumulate k in [32,64) and also handle decode +
// x staging. kh=1 partials go through smem (conflict-free [slot][thread]
// layout); kh=0 combines + does nonlinearities. Every warp is kh-uniform, so
// the hot-loop smem pattern is identical to round 9 (no bank conflicts).

#define B_   4096
#define T_   512
#define H_   64
#define RT   16      // rows per CTA
#define NT   256     // threads per CTA
#define HPD  18      // hdup row pitch in ulls (16 used + pad)
#define KH   32      // k per half

typedef unsigned long long ull;

__device__ __forceinline__ float tanhfast(float x) {
    float y; asm("tanh.approx.f32 %0, %1;" : "=f"(y) : "f"(x)); return y;
}
__device__ __forceinline__ float sigf(float x) {
    return fmaf(0.5f, tanhfast(0.5f * x), 0.5f);
}
__device__ __forceinline__ ull pack2(float a, float b) {   // a -> low lane
    ull r; asm("mov.b64 %0, {%1, %2};" : "=l"(r) : "f"(a), "f"(b)); return r;
}
__device__ __forceinline__ void unpack2(ull v, float& lo, float& hi) {
    asm("mov.b64 {%0, %1}, %2;" : "=f"(lo), "=f"(hi) : "l"(v));
}
__device__ __forceinline__ ull fma2(ull a, ull b, ull c) {
    ull d; asm("fma.rn.f32x2 %0, %1, %2, %3;" : "=l"(d) : "l"(a), "l"(b), "l"(c)); return d;
}
__device__ __forceinline__ ull add2(ull a, ull b) {
    ull d; asm("add.rn.f32x2 %0, %1, %2;" : "=l"(d) : "l"(a), "l"(b)); return d;
}

struct Smem {
    ulonglong2 W4[H_][H_];     // 64KB [k][u]: .x=(wi,wf) .y=(wg,wo)
    ull hdup[2][H_][HPD];      // 18KB [buf][unit][row]: (h,h) duplicated
    ulonglong2 part[8][128];   // 16KB kh=1 partials: [slot][hid], 16B lane stride
    ull xdup[2][3][RT];        // [buf][comp][row]: (x,x) duplicated
    float wdec[3][H_];
};
#define SMEM_BYTES ((int)sizeof(Smem))

extern __shared__ char smem_raw[];

__global__ void __launch_bounds__(NT, 2)
lstm_persistent_kernel(const float* __restrict__ x,      // [B, T, 3]
                       const float* __restrict__ Wih,    // [256, 3]
                       const float* __restrict__ Whh,    // [256, 64]
                       const float* __restrict__ bih,    // [256]
                       const float* __restrict__ bhh,    // [256]
                       const float* __restrict__ Wdec,   // [3, 64]
                       const float* __restrict__ bdec,   // [3]
                       float* __restrict__ out)          // [B, T, 3]
{
    Smem* S = (Smem*)smem_raw;
    const int tid  = threadIdx.x;
    const int row0 = blockIdx.x * RT;

    const int kh  = tid >> 7;       // 0: k in [0,32) + nonlin, 1: k in [32,64) + decode
    const int hid = tid & 127;      // id within half
    const int u   = hid >> 1;       // unit 0..63
    const int rg  = hid & 1;        // rows 8rg .. 8rg+7

    // ---- setup -----------------------------------------------------------
    for (int idx = tid; idx < H_ * H_; idx += NT) {
        const int k = idx >> 6, uu = idx & 63;
        const float wi = Whh[(0 * H_ + uu) * H_ + k];
        const float wf = Whh[(1 * H_ + uu) * H_ + k];
        const float wg = Whh[(2 * H_ + uu) * H_ + k];
        const float wo = Whh[(3 * H_ + uu) * H_ + k];
        *(float4*)&S->W4[k][uu] = make_float4(wi, wf, wg, wo);
    }
    for (int i = tid; i < 2 * H_ * HPD; i += NT) ((ull*)S->hdup)[i] = 0ull;
    for (int i = tid; i < 3 * H_; i += NT) ((float*)S->wdec)[i] = Wdec[i];

    // kh=0 needs bias + W_ih (gate-packed)
    const ull bias_if = pack2(bih[u]        + bhh[u],
                              bih[H_ + u]   + bhh[H_ + u]);
    const ull bias_go = pack2(bih[2*H_ + u] + bhh[2*H_ + u],
                              bih[3*H_ + u] + bhh[3*H_ + u]);
    ull wih_if[3], wih_go[3];
#pragma unroll
    for (int i = 0; i < 3; i++) {
        wih_if[i] = pack2(Wih[u * 3 + i],          Wih[(H_ + u) * 3 + i]);
        wih_go[i] = pack2(Wih[(2*H_ + u) * 3 + i], Wih[(3*H_ + u) * 3 + i]);
    }

    // decode / x-staging roles: kh=1, hid 0..47 -> (comp o, row r)
    const int o_ = hid >> 4;        // 0..2
    const int r_ = hid & 15;        // 0..15
    const bool is_dec = (kh == 1) && (hid < 48);
    float bd = 0.0f;
    if (is_dec) {
        bd = bdec[o_];
        const float xv = x[((size_t)(row0 + r_) * T_ + 0) * 3 + o_];
        S->xdup[0][o_][r_] = pack2(xv, xv);
    }

    float c[8];                     // kh=0 cell state for rows 8rg..8rg+7
#pragma unroll
    for (int p = 0; p < 8; p++) c[p] = 0.0f;

    __syncthreads();

    // ---- timestep loop -----------------------------------------------------
    for (int t = 0; t < T_; t++) {
        const int A = t & 1, Bb = A ^ 1;

        // issue x(t+1) prefetch early (LDG latency hidden under matvec)
        float xp = 0.0f;
        if (is_dec && (t + 1) < T_)
            xp = x[((size_t)(row0 + r_) * T_ + (t + 1)) * 3 + o_];

        // partial accumulators for rows 8rg+j, j=0..7
        ull aif[8], ago[8];
        if (kh == 0) {
#pragma unroll
            for (int j = 0; j < 8; j++) { aif[j] = bias_if; ago[j] = bias_go; }
#pragma unroll
            for (int i = 0; i < 3; i++) {
                const ulonglong2 xv = *(const ulonglong2*)&S->xdup[A][i][8 * rg];
                // xv.x packs rows (8rg, 8rg+1)? No: xdup is ull per row; take 2 rows per ull2
                // [8rg .. 8rg+1] in xv.{x,y}. Need 8 rows -> 4 ull2 loads:
                (void)xv;
                const ulonglong2* xpp = (const ulonglong2*)&S->xdup[A][i][8 * rg];
#pragma unroll
                for (int q = 0; q < 4; q++) {
                    const ulonglong2 xq = xpp[q];
                    aif[2*q]   = fma2(xq.x, wih_if[i], aif[2*q]);
                    ago[2*q]   = fma2(xq.x, wih_go[i], ago[2*q]);
                    aif[2*q+1] = fma2(xq.y, wih_if[i], aif[2*q+1]);
                    ago[2*q+1] = fma2(xq.y, wih_go[i], ago[2*q+1]);
                }
            }
        } else {
#pragma unroll
            for (int j = 0; j < 8; j++) { aif[j] = 0ull; ago[j] = 0ull; }
        }

        // partial recurrent matvec over my 32 k's: per k, 5x LDS.128 + 16x fma2
        {
            const ulonglong2* wp = &S->W4[KH * kh][u];       // stride H_ per k
            const ull* hp = &S->hdup[A][KH * kh][8 * rg];    // stride HPD per k
#pragma unroll 4
            for (int k = 0; k < KH; k++) {
                const ulonglong2 wv = *wp;
                const ulonglong2 h01 = *(const ulonglong2*)(hp + 0);
                const ulonglong2 h23 = *(const ulonglong2*)(hp + 2);
                const ulonglong2 h45 = *(const ulonglong2*)(hp + 4);
                const ulonglong2 h67 = *(const ulonglong2*)(hp + 6);
                aif[0] = fma2(h01.x, wv.x, aif[0]);
                ago[0] = fma2(h01.x, wv.y, ago[0]);
                aif[1] = fma2(h01.y, wv.x, aif[1]);
                ago[1] = fma2(h01.y, wv.y, ago[1]);
                aif[2] = fma2(h23.x, wv.x, aif[2]);
                ago[2] = fma2(h23.x, wv.y, ago[2]);
                aif[3] = fma2(h23.y, wv.x, aif[3]);
                ago[3] = fma2(h23.y, wv.y, ago[3]);
                aif[4] = fma2(h45.x, wv.x, aif[4]);
                ago[4] = fma2(h45.x, wv.y, ago[4]);
                aif[5] = fma2(h45.y, wv.x, aif[5]);
                ago[5] = fma2(h45.y, wv.y, ago[5]);
                aif[6] = fma2(h67.x, wv.x, aif[6]);
                ago[6] = fma2(h67.x, wv.y, ago[6]);
                aif[7] = fma2(h67.y, wv.x, aif[7]);
                ago[7] = fma2(h67.y, wv.y, ago[7]);
                wp += H_;
                hp += HPD;
            }
        }

        if (kh == 1) {
            // store partials: [slot][hid], 16B lane stride -> conflict-free STS.128
            ulonglong2 v;
            v.x = aif[0]; v.y = aif[1]; S->part[0][hid] = v;
            v.x = aif[2]; v.y = aif[3]; S->part[1][hid] = v;
            v.x = aif[4]; v.y = aif[5]; S->part[2][hid] = v;
            v.x = aif[6]; v.y = aif[7]; S->part[3][hid] = v;
            v.x = ago[0]; v.y = ago[1]; S->part[4][hid] = v;
            v.x = ago[2]; v.y = ago[3]; S->part[5][hid] = v;
            v.x = ago[4]; v.y = ago[5]; S->part[6][hid] = v;
            v.x = ago[6]; v.y = ago[7]; S->part[7][hid] = v;

            // decode previous step's h -> out[., t-1, .] (reads hdup[A], still valid)
            if (is_dec) {
                if (t > 0) {
                    const float* hp_ = (const float*)&S->hdup[A][0][r_];  // low lane of (h,h)
                    const float* wd  = &S->wdec[o_][0];
                    float s0 = 0.f, s1 = 0.f, s2 = 0.f, s3 = 0.f;
#pragma unroll 4
                    for (int k = 0; k < H_; k += 4) {
                        s0 = fmaf(hp_[(k + 0) * (2 * HPD)], wd[k + 0], s0);
                        s1 = fmaf(hp_[(k + 1) * (2 * HPD)], wd[k + 1], s1);
                        s2 = fmaf(hp_[(k + 2) * (2 * HPD)], wd[k + 2], s2);
                        s3 = fmaf(hp_[(k + 3) * (2 * HPD)], wd[k + 3], s3);
                    }
                    out[((size_t)(row0 + r_) * T_ + (t - 1)) * 3 + o_] = (s0 + s1) + (s2 + s3) + bd;
                }
                // stage x(t+1), duplicated
                S->xdup[Bb][o_][r_] = pack2(xp, xp);
            }
        }

        __syncthreads();   // partials + x(t+1) visible; everyone done with hdup[A]

        if (kh == 0) {
            // combine with kh=1 partial
            ulonglong2 p;
            p = S->part[0][hid]; aif[0] = add2(aif[0], p.x); aif[1] = add2(aif[1], p.y);
            p = S->part[1][hid]; aif[2] = add2(aif[2], p.x); aif[3] = add2(aif[3], p.y);
            p = S->part[2][hid]; aif[4] = add2(aif[4], p.x); aif[5] = add2(aif[5], p.y);
            p = S->part[3][hid]; aif[6] = add2(aif[6], p.x); aif[7] = add2(aif[7], p.y);
            p = S->part[4][hid]; ago[0] = add2(ago[0], p.x); ago[1] = add2(ago[1], p.y);
            p = S->part[5][hid]; ago[2] = add2(ago[2], p.x); ago[3] = add2(ago[3], p.y);
            p = S->part[6][hid]; ago[4] = add2(ago[4], p.x); ago[5] = add2(ago[5], p.y);
            p = S->part[7][hid]; ago[6] = add2(ago[6], p.x); ago[7] = add2(ago[7], p.y);

            // nonlinearities + state update on 8 (row, unit u) cells
            float hout[8];
#pragma unroll
            for (int j = 0; j < 8; j++) {
                float gi, gf, gg, go;
                unpack2(aif[j], gi, gf);
                unpack2(ago[j], gg, go);
                const float ig = sigf(gi), fg = sigf(gf);
                const float gt = tanhfast(gg), og = sigf(go);
                const float cn = fmaf(fg, c[j], ig * gt);
                c[j] = cn;
                hout[j] = og * tanhfast(cn);
            }
            ull* hd = &S->hdup[Bb][u][8 * rg];
#pragma unroll
            for (int q = 0; q < 4; q++) {
                ulonglong2 v2;
                v2.x = pack2(hout[2*q],     hout[2*q]);
                v2.y = pack2(hout[2*q + 1], hout[2*q + 1]);
                *(ulonglong2*)(hd + 2*q) = v2;
            }
        }

        __syncthreads();   // h(t) visible to both halves
    }

    // epilogue: decode h(T-1) (last store went to buffer 0)
    if (is_dec) {
        const float* hp_ = (const float*)&S->hdup[0][0][r_];
        const float* wd  = &S->wdec[o_][0];
        float s0 = 0.f, s1 = 0.f, s2 = 0.f, s3 = 0.f;
#pragma unroll 4
        for (int k = 0; k < H_; k += 4) {
            s0 = fmaf(hp_[(k + 0) * (2 * HPD)], wd[k + 0], s0);
            s1 = fmaf(hp_[(k + 1) * (2 * HPD)], wd[k + 1], s1);
            s2 = fmaf(hp_[(k + 2) * (2 * HPD)], wd[k + 2], s2);
            s3 = fmaf(hp_[(k + 3) * (2 * HPD)], wd[k + 3], s3);
        }
        out[((size_t)(row0 + r_) * T_ + (T_ - 1)) * 3 + o_] = (s0 + s1) + (s2 + s3) + bd;
    }
}

extern "C" void kernel_launch(void* const* d_in, const int* in_sizes, int n_in,
                              void* d_out, int out_size) {
    const float* x    = (const float*)d_in[0];
    const float* Wih  = (const float*)d_in[1];
    const float* Whh  = (const float*)d_in[2];
    const float* bih  = (const float*)d_in[3];
    const float* bhh  = (const float*)d_in[4];
    const float* Wdec = (const float*)d_in[5];
    const float* bdec = (const float*)d_in[6];
    float* out = (float*)d_out;

    cudaFuncSetAttribute(lstm_persistent_kernel,
                         cudaFuncAttributeMaxDynamicSharedMemorySize, SMEM_BYTES);
    lstm_persistent_kernel<<<B_ / RT, NT, SMEM_BYTES>>>(x, Wih, Whh, bih, bhh, Wdec, bdec, out);
}